// round 1
// baseline (speedup 1.0000x reference)
#include <cuda_runtime.h>
#include <math.h>

#define NN 100000
#define FF 128
#define EE 600000
#define GG 1000
#define EPS 1e-5f
#define NB_SCAN ((NN + 1023) / 1024)   // 98

// ---------------- scratch (__device__ globals; no allocation allowed) -------
__device__ __align__(16) float g_batch_s[FF];
__device__ __align__(16) float g_batch_s2[FF];
__device__ __align__(16) float g_batch_mu[FF];
__device__ __align__(16) float g_batch_rs[FF];
__device__ __align__(16) float g_lamw[4 * FF];
__device__ __align__(16) float g_graph_s[GG * FF];
__device__ __align__(16) float g_graph_s2[GG * FF];
__device__ int g_gcnt[GG];
__device__ int g_deg[NN];
__device__ int g_incl[NN];
__device__ int g_bsum[NB_SCAN];
__device__ int g_boff[NB_SCAN];
__device__ int g_off[NN + 1];
__device__ int g_cur[NN];
__device__ int g_csr[EE];

// ---------------- helpers ---------------------------------------------------
__device__ __forceinline__ void f4load(float* a, const float* p) {
    float4 v = *reinterpret_cast<const float4*>(p);
    a[0] = v.x; a[1] = v.y; a[2] = v.z; a[3] = v.w;
}

// ---------------- K0: zero scratch ------------------------------------------
__global__ void zero_kernel() {
    int i = blockIdx.x * blockDim.x + threadIdx.x;
    int stride = gridDim.x * blockDim.x;
    for (int j = i; j < GG * FF; j += stride) { g_graph_s[j] = 0.f; g_graph_s2[j] = 0.f; }
    for (int j = i; j < NN; j += stride) { g_deg[j] = 0; g_cur[j] = 0; }
    for (int j = i; j < GG; j += stride) g_gcnt[j] = 0;
    for (int j = i; j < FF; j += stride) { g_batch_s[j] = 0.f; g_batch_s2[j] = 0.f; }
}

// ---------------- K1: batch + graph stats (graph_id is sorted) --------------
// blockDim (128, 4): thread.x = feature, thread.y = 64-row sub-chunk.
__global__ void stats_kernel(const float* __restrict__ x, const int* __restrict__ gid) {
    __shared__ float sb[4][FF];
    __shared__ float sb2[4][FF];
    int f = threadIdx.x;
    int sub = threadIdx.y;
    int row0 = blockIdx.x * 256 + sub * 64;
    float bs = 0.f, bs2 = 0.f;
    if (row0 < NN) {
        int row1 = min(row0 + 64, NN);
        int curg = gid[row0];
        float gs = 0.f, gs2 = 0.f;
        int cnt = 0;
        for (int r = row0; r < row1; ++r) {
            int g = gid[r];
            float v = x[(size_t)r * FF + f];
            if (g != curg) {
                atomicAdd(&g_graph_s[curg * FF + f], gs);
                atomicAdd(&g_graph_s2[curg * FF + f], gs2);
                if (f == 0) atomicAdd(&g_gcnt[curg], cnt);
                gs = 0.f; gs2 = 0.f; cnt = 0; curg = g;
            }
            gs += v; gs2 += v * v;
            bs += v; bs2 += v * v;
            cnt++;
        }
        atomicAdd(&g_graph_s[curg * FF + f], gs);
        atomicAdd(&g_graph_s2[curg * FF + f], gs2);
        if (f == 0) atomicAdd(&g_gcnt[curg], cnt);
    }
    sb[sub][f] = bs;
    sb2[sub][f] = bs2;
    __syncthreads();
    if (sub == 0) {
        float t = sb[0][f] + sb[1][f] + sb[2][f] + sb[3][f];
        float t2 = sb2[0][f] + sb2[1][f] + sb2[2][f] + sb2[3][f];
        atomicAdd(&g_batch_s[f], t);
        atomicAdd(&g_batch_s2[f], t2);
    }
}

// ---------------- K2a: in-degree histogram ----------------------------------
__global__ void deg_kernel(const int* __restrict__ dst) {
    int e = blockIdx.x * blockDim.x + threadIdx.x;
    if (e < EE) atomicAdd(&g_deg[dst[e]], 1);
}

// ---------------- K2b: exclusive scan of deg -> offsets ---------------------
__global__ void scan1_kernel() {
    __shared__ int s[1024];
    int t = threadIdx.x;
    int i = blockIdx.x * 1024 + t;
    int d = (i < NN) ? g_deg[i] : 0;
    s[t] = d;
    __syncthreads();
    for (int off = 1; off < 1024; off <<= 1) {
        int u = (t >= off) ? s[t - off] : 0;
        __syncthreads();
        s[t] += u;
        __syncthreads();
    }
    if (i < NN) g_incl[i] = s[t];
    if (t == 1023) g_bsum[blockIdx.x] = s[1023];
}

__global__ void scan2_kernel() {
    __shared__ int s[128];
    int t = threadIdx.x;
    int v = (t < NB_SCAN) ? g_bsum[t] : 0;
    s[t] = v;
    __syncthreads();
    for (int off = 1; off < 128; off <<= 1) {
        int u = (t >= off) ? s[t - off] : 0;
        __syncthreads();
        s[t] += u;
        __syncthreads();
    }
    if (t < NB_SCAN) g_boff[t] = s[t] - v;  // exclusive
}

__global__ void scan3_kernel() {
    int i = blockIdx.x * blockDim.x + threadIdx.x;
    if (i < NN) {
        int inc = g_boff[i >> 10] + g_incl[i];
        g_off[i] = inc - g_deg[i];
        if (i == NN - 1) g_off[NN] = inc;
    }
}

// ---------------- K2c: scatter edges into CSR slots -------------------------
__global__ void scatter_kernel(const int* __restrict__ src, const int* __restrict__ dst) {
    int e = blockIdx.x * blockDim.x + threadIdx.x;
    if (e < EE) {
        int d = dst[e];
        int p = g_off[d] + atomicAdd(&g_cur[d], 1);
        g_csr[p] = src[e];
    }
}

// ---------------- Kf: finalize batch stats + lambda softmax (1 block) -------
__global__ void small_kernel(const float* __restrict__ lb, const float* __restrict__ lg,
                             const float* __restrict__ la, const float* __restrict__ ln) {
    int f = threadIdx.x;  // 128 threads
    float mu = g_batch_s[f] * (1.0f / NN);
    float var = g_batch_s2[f] * (1.0f / NN) - mu * mu;
    g_batch_mu[f] = mu;
    g_batch_rs[f] = rsqrtf(fmaxf(var, 0.f) + EPS);
    float a = lb[f], b = lg[f], c = la[f], d = ln[f];
    float m = fmaxf(fmaxf(a, b), fmaxf(c, d));
    float ea = expf(a - m), eb = expf(b - m), ec = expf(c - m), ed = expf(d - m);
    float inv = 1.f / (ea + eb + ec + ed);
    g_lamw[0 * FF + f] = ea * inv;
    g_lamw[1 * FF + f] = eb * inv;
    g_lamw[2 * FF + f] = ec * inv;
    g_lamw[3 * FF + f] = ed * inv;
}

// ---------------- K3: fused finalize, warp per node -------------------------
__global__ void __launch_bounds__(256) main_kernel(
    const float* __restrict__ x, const float* __restrict__ gamma,
    const float* __restrict__ beta, const int* __restrict__ gid,
    float* __restrict__ out) {
    int warp = (blockIdx.x * blockDim.x + threadIdx.x) >> 5;
    int lane = threadIdx.x & 31;
    if (warp >= NN) return;
    int i = warp;
    int fo = lane * 4;

    float xv[4];
    f4load(xv, x + (size_t)i * FF + fo);

    // node norm (LayerNorm over F)
    float ps = xv[0] + xv[1] + xv[2] + xv[3];
    float ps2 = xv[0] * xv[0] + xv[1] * xv[1] + xv[2] * xv[2] + xv[3] * xv[3];
#pragma unroll
    for (int o = 16; o > 0; o >>= 1) {
        ps += __shfl_xor_sync(0xffffffffu, ps, o);
        ps2 += __shfl_xor_sync(0xffffffffu, ps2, o);
    }
    float mu_n = ps * (1.f / FF);
    float rs_n = rsqrtf(fmaxf(ps2 * (1.f / FF) - mu_n * mu_n, 0.f) + EPS);

    // graph norm stats
    int g = gid[i];
    float gsv[4], gs2v[4];
    f4load(gsv, g_graph_s + g * FF + fo);
    f4load(gs2v, g_graph_s2 + g * FF + fo);
    float icg = 1.f / (float)max(g_gcnt[g], 1);
    float mug[4], rsg[4];
#pragma unroll
    for (int j = 0; j < 4; ++j) {
        mug[j] = gsv[j] * icg;
        rsg[j] = rsqrtf(fmaxf(gs2v[j] * icg - mug[j] * mug[j], 0.f) + EPS);
    }

    // adjacency stats: gather in-neighbor rows via CSR (x is L2-resident)
    int beg = g_off[i], end = g_off[i + 1];
    float as[4] = {0.f, 0.f, 0.f, 0.f}, as2[4] = {0.f, 0.f, 0.f, 0.f};
    int e = beg;
    for (; e + 1 < end; e += 2) {
        int s0 = g_csr[e], s1 = g_csr[e + 1];
        float v0[4], v1[4];
        f4load(v0, x + (size_t)s0 * FF + fo);
        f4load(v1, x + (size_t)s1 * FF + fo);
#pragma unroll
        for (int j = 0; j < 4; ++j) {
            as[j] += v0[j] + v1[j];
            as2[j] += v0[j] * v0[j] + v1[j] * v1[j];
        }
    }
    if (e < end) {
        int s0 = g_csr[e];
        float v0[4];
        f4load(v0, x + (size_t)s0 * FF + fo);
#pragma unroll
        for (int j = 0; j < 4; ++j) {
            as[j] += v0[j];
            as2[j] += v0[j] * v0[j];
        }
    }
    float idc = 1.f / (float)max(end - beg, 1);
    float mua[4], rsa[4];
#pragma unroll
    for (int j = 0; j < 4; ++j) {
        mua[j] = as[j] * idc;
        rsa[j] = rsqrtf(fmaxf(as2[j] * idc - mua[j] * mua[j], 0.f) + EPS);
    }

    // batch stats, lambda weights, affine
    float bmu[4], brs[4], l0[4], l1[4], l2[4], l3[4], gm[4], bt[4];
    f4load(bmu, g_batch_mu + fo);
    f4load(brs, g_batch_rs + fo);
    f4load(l0, g_lamw + 0 * FF + fo);
    f4load(l1, g_lamw + 1 * FF + fo);
    f4load(l2, g_lamw + 2 * FF + fo);
    f4load(l3, g_lamw + 3 * FF + fo);
    f4load(gm, gamma + fo);
    f4load(bt, beta + fo);

    float4 o4;
    float ov[4];
#pragma unroll
    for (int j = 0; j < 4; ++j) {
        float xb = (xv[j] - bmu[j]) * brs[j];
        float xg = (xv[j] - mug[j]) * rsg[j];
        float xa = (xv[j] - mua[j]) * rsa[j];
        float xn = (xv[j] - mu_n) * rs_n;
        ov[j] = gm[j] * (l0[j] * xb + l1[j] * xg + l2[j] * xa + l3[j] * xn) + bt[j];
    }
    o4.x = ov[0]; o4.y = ov[1]; o4.z = ov[2]; o4.w = ov[3];
    *reinterpret_cast<float4*>(out + (size_t)i * FF + fo) = o4;
}

// ---------------- launch ----------------------------------------------------
extern "C" void kernel_launch(void* const* d_in, const int* in_sizes, int n_in,
                              void* d_out, int out_size) {
    const float* x = (const float*)d_in[0];
    const float* gamma = (const float*)d_in[1];
    const float* beta = (const float*)d_in[2];
    const float* lb = (const float*)d_in[3];
    const float* lg = (const float*)d_in[4];
    const float* la = (const float*)d_in[5];
    const float* ln = (const float*)d_in[6];
    const int* gid = (const int*)d_in[7];
    const int* esrc = (const int*)d_in[8];
    const int* edst = (const int*)d_in[9];
    float* out = (float*)d_out;

    zero_kernel<<<512, 256>>>();

    dim3 sblk(128, 4);
    stats_kernel<<<(NN + 255) / 256, sblk>>>(x, gid);

    deg_kernel<<<(EE + 255) / 256, 256>>>(edst);
    scan1_kernel<<<NB_SCAN, 1024>>>();
    scan2_kernel<<<1, 128>>>();
    scan3_kernel<<<(NN + 255) / 256, 256>>>();
    scatter_kernel<<<(EE + 255) / 256, 256>>>(esrc, edst);

    small_kernel<<<1, 128>>>(lb, lg, la, ln);

    main_kernel<<<(NN * 32 + 255) / 256, 256>>>(x, gamma, beta, gid, out);
}